// round 1
// baseline (speedup 1.0000x reference)
#include <cuda_runtime.h>
#include <cuda_bf16.h>
#include <cstdint>
#include <cstddef>

// Problem constants
#define NN 50000
#define EE 800000
#define FIN 256
#define HID 128
#define HEADS 4
#define NGRAPH 50
#define NEG_SLOPE 0.2f

// ---------------- scratch (device globals; no allocation allowed) -------------
__device__ float g_h[(size_t)NN * HEADS * HID];     // GEMM output per layer (max 50000*512)
__device__ float g_act[(size_t)NN * HEADS * HID];   // aggregated output / next-layer input
__device__ float g_as[NN * HEADS];
__device__ float g_ad[NN * HEADS];
__device__ float g_emax[NN * HEADS];
__device__ float g_denom[NN * HEADS];
__device__ float g_ex[(size_t)EE * HEADS];          // e then ex, per edge per head
__device__ float g_pool[NGRAPH * HID];
__device__ float g_cnt[NGRAPH];

// ---------------- SGEMM: C[M,N] = A[M,K] @ B[K,N], fp32, row-major ------------
// BM=128 BN=128 BK=8, 256 threads, 8x8 per thread. Requires K%8==0, N%128==0.
#define BM 128
#define BN 128
#define BK 8
#define TM 8
#define TN 8

__global__ __launch_bounds__(256) void sgemm_kernel(
    const float* __restrict__ A, const float* __restrict__ B, float* __restrict__ C,
    int M, int K, int N)
{
    __shared__ float As[BK][BM];
    __shared__ float Bs[BK][BN];

    const int bx = blockIdx.x;      // N tile
    const int by = blockIdx.y;      // M tile
    const int tid = threadIdx.x;
    const int tx = tid % 16;
    const int ty = tid / 16;

    float acc[TM][TN];
#pragma unroll
    for (int i = 0; i < TM; i++)
#pragma unroll
        for (int j = 0; j < TN; j++) acc[i][j] = 0.0f;

    const int aRow = tid >> 1;            // 0..127
    const int aCol = (tid & 1) * 4;       // 0 or 4
    const int bRow = tid >> 5;            // 0..7
    const int bCol = (tid & 31) * 4;      // 0..124

    const int mBase = by * BM;

    for (int k0 = 0; k0 < K; k0 += BK) {
        // load A tile (transposed into As[k][m])
        int gr = mBase + aRow;
        float4 av = make_float4(0.f, 0.f, 0.f, 0.f);
        if (gr < M) av = *(const float4*)&A[(size_t)gr * K + k0 + aCol];
        As[aCol + 0][aRow] = av.x;
        As[aCol + 1][aRow] = av.y;
        As[aCol + 2][aRow] = av.z;
        As[aCol + 3][aRow] = av.w;
        // load B tile
        float4 bv = *(const float4*)&B[(size_t)(k0 + bRow) * N + bx * BN + bCol];
        *(float4*)&Bs[bRow][bCol] = bv;
        __syncthreads();

#pragma unroll
        for (int k = 0; k < BK; k++) {
            float ra[TM], rb[TN];
#pragma unroll
            for (int i = 0; i < TM; i++) ra[i] = As[k][ty * TM + i];
#pragma unroll
            for (int j = 0; j < TN; j++) rb[j] = Bs[k][tx * TN + j];
#pragma unroll
            for (int i = 0; i < TM; i++)
#pragma unroll
                for (int j = 0; j < TN; j++) acc[i][j] += ra[i] * rb[j];
        }
        __syncthreads();
    }

#pragma unroll
    for (int i = 0; i < TM; i++) {
        int gr = mBase + ty * TM + i;
        if (gr < M) {
#pragma unroll
            for (int j = 0; j < TN; j += 4) {
                *(float4*)&C[(size_t)gr * N + bx * BN + tx * TN + j] =
                    make_float4(acc[i][j], acc[i][j + 1], acc[i][j + 2], acc[i][j + 3]);
            }
        }
    }
}

// ---------------- per-node attention logits: alpha_s/d[n,h] = <h[n,h,:], a[h,:]> ----
__global__ void alpha_kernel(const float* __restrict__ h,
                             const float* __restrict__ a_s, const float* __restrict__ a_d,
                             float* __restrict__ as_out, float* __restrict__ ad_out,
                             int heads, int ch)
{
    int node = blockIdx.x;
    int w = threadIdx.x >> 5;
    int lane = threadIdx.x & 31;
    if (w >= heads) return;
    const float* hp = h + (size_t)node * heads * ch + w * ch;
    const float* asp = a_s + w * ch;
    const float* adp = a_d + w * ch;
    float ss = 0.f, sd = 0.f;
    for (int c = lane; c < ch; c += 32) {
        float v = hp[c];
        ss += v * asp[c];
        sd += v * adp[c];
    }
#pragma unroll
    for (int o = 16; o; o >>= 1) {
        ss += __shfl_xor_sync(0xffffffffu, ss, o);
        sd += __shfl_xor_sync(0xffffffffu, sd, o);
    }
    if (lane == 0) {
        as_out[node * heads + w] = ss;
        ad_out[node * heads + w] = sd;
    }
}

__global__ void fill_neginf_kernel(float* __restrict__ p, int n)
{
    int i = blockIdx.x * blockDim.x + threadIdx.x;
    if (i < n) p[i] = -__int_as_float(0x7f800000); // -inf
}

__device__ __forceinline__ void atomicMaxFloat(float* addr, float value)
{
    if (value >= 0.f)
        atomicMax((int*)addr, __float_as_int(value));
    else
        atomicMin((unsigned int*)addr, __float_as_uint(value));
}

// pass 1: e = leaky_relu(as[src]+ad[dst]); store; segment max into emax[dst]
__global__ void edge_e_kernel(const int* __restrict__ src, const int* __restrict__ dst,
                              const float* __restrict__ as_, const float* __restrict__ ad_,
                              float* __restrict__ e_out, float* __restrict__ emax,
                              int E, int heads)
{
    int e = blockIdx.x * blockDim.x + threadIdx.x;
    if (e >= E) return;
    int s = src[e], d = dst[e];
#pragma unroll 4
    for (int h = 0; h < heads; h++) {
        float v = as_[s * heads + h] + ad_[d * heads + h];
        v = (v >= 0.f) ? v : NEG_SLOPE * v;
        e_out[(size_t)e * heads + h] = v;
        atomicMaxFloat(&emax[d * heads + h], v);
    }
}

// pass 2: ex = exp(e - emax[dst]); store; segment sum into denom[dst]
__global__ void edge_exp_kernel(const int* __restrict__ dst,
                                float* __restrict__ e_buf, const float* __restrict__ emax,
                                float* __restrict__ denom, int E, int heads)
{
    int e = blockIdx.x * blockDim.x + threadIdx.x;
    if (e >= E) return;
    int d = dst[e];
#pragma unroll 4
    for (int h = 0; h < heads; h++) {
        float ex = expf(e_buf[(size_t)e * heads + h] - emax[d * heads + h]);
        e_buf[(size_t)e * heads + h] = ex;
        atomicAdd(&denom[d * heads + h], ex);
    }
}

// pass 3: out[dst,h,c] += h[src,h,c] * ex/(denom[dst,h]+eps). One block per edge.
__global__ void scatter_kernel(const int* __restrict__ src, const int* __restrict__ dst,
                               const float* __restrict__ hbuf, const float* __restrict__ exbuf,
                               const float* __restrict__ denom, float* __restrict__ out,
                               int heads, int ch)
{
    __shared__ float coeff[8];
    int e = blockIdx.x;
    int t = threadIdx.x;   // 0..ch-1
    int s = src[e], d = dst[e];
    if (t < heads)
        coeff[t] = exbuf[(size_t)e * heads + t] / (denom[d * heads + t] + 1e-16f);
    __syncthreads();
    const float* hp = hbuf + (size_t)s * heads * ch;
    float* op = out + (size_t)d * heads * ch;
    for (int h = 0; h < heads; h++)
        atomicAdd(&op[h * ch + t], hp[h * ch + t] * coeff[h]);
}

// bias add + optional elu, in place
__global__ void bias_act_kernel(float* __restrict__ buf, const float* __restrict__ bias,
                                size_t total, int width, int do_elu)
{
    size_t i = (size_t)blockIdx.x * blockDim.x + threadIdx.x;
    if (i >= total) return;
    float v = buf[i] + bias[i % width];
    if (do_elu) v = (v > 0.f) ? v : expm1f(v);
    buf[i] = v;
}

// graph pooling
__global__ void pool_sum_kernel(const float* __restrict__ node_emb, const int* __restrict__ batch,
                                float* __restrict__ pool, float* __restrict__ cnt, int n)
{
    int node = blockIdx.x;
    int t = threadIdx.x;   // 0..127
    int g = batch[node];
    atomicAdd(&pool[g * HID + t], node_emb[(size_t)node * HID + t]);
    if (t == 0) atomicAdd(&cnt[g], 1.0f);
}

__global__ void pool_div_kernel(const float* __restrict__ pool, const float* __restrict__ cnt,
                                float* __restrict__ out)
{
    int i = blockIdx.x * blockDim.x + threadIdx.x;
    if (i >= NGRAPH * HID) return;
    int g = i / HID;
    float c = cnt[g];
    out[i] = pool[i] / fmaxf(c, 1.0f);
}

// ---------------- host side ----------------
static void run_gat_layer(const float* in, int fin,
                          const float* W, const float* a_s, const float* a_d, const float* bias,
                          int heads, float* out, int do_elu,
                          int n, int E, const int* src, const int* dst,
                          float* hbuf, float* asb, float* adb, float* emaxb, float* denomb, float* exb)
{
    const int ch = HID;
    const int width = heads * ch;

    // GEMM: hbuf = in @ W
    dim3 ggrid((width + BN - 1) / BN, (n + BM - 1) / BM);
    sgemm_kernel<<<ggrid, 256>>>(in, W, hbuf, n, fin, width);

    // attention logits per node
    alpha_kernel<<<n, heads * 32>>>(hbuf, a_s, a_d, asb, adb, heads, ch);

    // init segment buffers
    int nh = n * heads;
    fill_neginf_kernel<<<(nh + 255) / 256, 256>>>(emaxb, nh);
    cudaMemsetAsync(denomb, 0, (size_t)nh * sizeof(float));
    cudaMemsetAsync(out, 0, (size_t)n * width * sizeof(float));

    // edge passes
    edge_e_kernel<<<(E + 255) / 256, 256>>>(src, dst, asb, adb, exb, emaxb, E, heads);
    edge_exp_kernel<<<(E + 255) / 256, 256>>>(dst, exb, emaxb, denomb, E, heads);
    scatter_kernel<<<E, ch>>>(src, dst, hbuf, exb, denomb, out, heads, ch);

    // bias + activation
    size_t total = (size_t)n * width;
    bias_act_kernel<<<(int)((total + 255) / 256), 256>>>(out, bias, total, width, do_elu);
}

extern "C" void kernel_launch(void* const* d_in, const int* in_sizes, int n_in,
                              void* d_out, int out_size)
{
    const float* x     = (const float*)d_in[0];
    const int*   ei    = (const int*)d_in[1];
    const int*   batch = (const int*)d_in[2];
    const float* W1  = (const float*)d_in[3];
    const float* a1s = (const float*)d_in[4];
    const float* a1d = (const float*)d_in[5];
    const float* b1  = (const float*)d_in[6];
    const float* W2  = (const float*)d_in[7];
    const float* a2s = (const float*)d_in[8];
    const float* a2d = (const float*)d_in[9];
    const float* b2  = (const float*)d_in[10];
    const float* W3  = (const float*)d_in[11];
    const float* a3s = (const float*)d_in[12];
    const float* a3d = (const float*)d_in[13];
    const float* b3  = (const float*)d_in[14];

    const int n = in_sizes[0] / FIN;
    const int E = in_sizes[1] / 2;
    const int* src = ei;
    const int* dst = ei + E;

    float *hbuf, *actbuf, *asb, *adb, *emaxb, *denomb, *exb, *poolb, *cntb;
    cudaGetSymbolAddress((void**)&hbuf,  g_h);
    cudaGetSymbolAddress((void**)&actbuf, g_act);
    cudaGetSymbolAddress((void**)&asb,   g_as);
    cudaGetSymbolAddress((void**)&adb,   g_ad);
    cudaGetSymbolAddress((void**)&emaxb, g_emax);
    cudaGetSymbolAddress((void**)&denomb, g_denom);
    cudaGetSymbolAddress((void**)&exb,   g_ex);
    cudaGetSymbolAddress((void**)&poolb, g_pool);
    cudaGetSymbolAddress((void**)&cntb,  g_cnt);

    float* node_emb = (float*)d_out;               // [n, HID]
    float* graph_emb = (float*)d_out + (size_t)n * HID;  // [NGRAPH, HID]

    // Layer 1: x [n,256] -> act [n,512], elu
    run_gat_layer(x, FIN, W1, a1s, a1d, b1, HEADS, actbuf, 1,
                  n, E, src, dst, hbuf, asb, adb, emaxb, denomb, exb);

    // Layer 2: act [n,512] -> act [n,512], elu  (GEMM reads act into hbuf first)
    run_gat_layer(actbuf, HEADS * HID, W2, a2s, a2d, b2, HEADS, actbuf, 1,
                  n, E, src, dst, hbuf, asb, adb, emaxb, denomb, exb);

    // Layer 3: act [n,512] -> node_emb [n,128], heads=1, no elu
    run_gat_layer(actbuf, HEADS * HID, W3, a3s, a3d, b3, 1, node_emb, 0,
                  n, E, src, dst, hbuf, asb, adb, emaxb, denomb, exb);

    // Global mean pool per graph
    cudaMemsetAsync(poolb, 0, NGRAPH * HID * sizeof(float));
    cudaMemsetAsync(cntb, 0, NGRAPH * sizeof(float));
    pool_sum_kernel<<<n, HID>>>(node_emb, batch, poolb, cntb, n);
    pool_div_kernel<<<(NGRAPH * HID + 127) / 128, 128>>>(poolb, cntb, graph_emb);
}

// round 2
// speedup vs baseline: 4.3165x; 4.3165x over previous
#include <cuda_runtime.h>
#include <cuda_bf16.h>
#include <cstdint>
#include <cstddef>

#define NN 50000
#define EE 800000
#define FIN 256
#define HID 128
#define HEADS 4
#define NGRAPH 50
#define NEG_SLOPE 0.2f

// ---------------- scratch (device globals; no allocation allowed) -------------
__device__ float g_h[(size_t)NN * HEADS * HID];     // GEMM output per layer
__device__ float g_act[(size_t)NN * HEADS * HID];   // aggregated output / next input
__device__ float g_as[NN * HEADS];
__device__ float g_ad[NN * HEADS];
__device__ int   g_deg[NN];
__device__ int   g_rowstart[NN + 1];
__device__ int   g_cursor[NN];
__device__ int   g_csr_src[EE];
__device__ float g_pool[NGRAPH * HID];
__device__ float g_cnt[NGRAPH];

// ==================== TF32 tensor-core GEMM ====================
// C[M,N] = A[M,K] @ B[K,N], row-major fp32 in/out, tf32 mma accumulate fp32.
// Block tile 128x128, BK=32, 256 threads = 8 warps (2 m x 4 n), warp tile 64x32.

__device__ __forceinline__ float to_tf32(float x) {
    float y;
    asm("cvt.rna.tf32.f32 %0, %1;" : "=f"(y) : "f"(x));
    return y;
}

__global__ __launch_bounds__(256) void tf32_gemm_kernel(
    const float* __restrict__ A, const float* __restrict__ B, float* __restrict__ C,
    int M, int K, int N)
{
    __shared__ __align__(16) float As[128][36];   // [m][k], pad 4
    __shared__ __align__(16) float Bs[32][136];   // [k][n], pad 8

    const int tid  = threadIdx.x;
    const int lane = tid & 31;
    const int warp = tid >> 5;
    const int wm = (warp & 1) * 64;   // warp m offset in tile
    const int wn = (warp >> 1) * 32;  // warp n offset in tile

    const int mBase = blockIdx.y * 128;
    const int nBase = blockIdx.x * 128;

    float c[4][4][4];
#pragma unroll
    for (int mi = 0; mi < 4; mi++)
#pragma unroll
        for (int ni = 0; ni < 4; ni++)
#pragma unroll
            for (int q = 0; q < 4; q++) c[mi][ni][q] = 0.f;

    // A loads: 4 passes of 32 rows; thread -> row tid/8, col (tid%8)*4
    const int arow = tid >> 3;
    const int acol = (tid & 7) * 4;
    // B loads: 4 passes of 8 rows; thread -> row tid/32, col (tid%32)*4
    const int brow = tid >> 5;
    const int bcol = (tid & 31) * 4;

    for (int k0 = 0; k0 < K; k0 += 32) {
#pragma unroll
        for (int p = 0; p < 4; p++) {
            int r = arow + p * 32;
            int gr = mBase + r;
            float4 v = make_float4(0.f, 0.f, 0.f, 0.f);
            if (gr < M) v = *(const float4*)&A[(size_t)gr * K + k0 + acol];
            As[r][acol + 0] = to_tf32(v.x);
            As[r][acol + 1] = to_tf32(v.y);
            As[r][acol + 2] = to_tf32(v.z);
            As[r][acol + 3] = to_tf32(v.w);
        }
#pragma unroll
        for (int p = 0; p < 4; p++) {
            int r = brow + p * 8;
            float4 v = *(const float4*)&B[(size_t)(k0 + r) * N + nBase + bcol];
            Bs[r][bcol + 0] = to_tf32(v.x);
            Bs[r][bcol + 1] = to_tf32(v.y);
            Bs[r][bcol + 2] = to_tf32(v.z);
            Bs[r][bcol + 3] = to_tf32(v.w);
        }
        __syncthreads();

#pragma unroll
        for (int kk = 0; kk < 32; kk += 8) {
            uint32_t a[4][4], b[4][2];
            const int g = lane >> 2;   // group id 0..7
            const int l = lane & 3;    // id in group 0..3
#pragma unroll
            for (int mi = 0; mi < 4; mi++) {
                int r = wm + mi * 16 + g;
                a[mi][0] = __float_as_uint(As[r][kk + l]);
                a[mi][1] = __float_as_uint(As[r + 8][kk + l]);
                a[mi][2] = __float_as_uint(As[r][kk + l + 4]);
                a[mi][3] = __float_as_uint(As[r + 8][kk + l + 4]);
            }
#pragma unroll
            for (int ni = 0; ni < 4; ni++) {
                int ncol = wn + ni * 8 + g;
                b[ni][0] = __float_as_uint(Bs[kk + l][ncol]);
                b[ni][1] = __float_as_uint(Bs[kk + l + 4][ncol]);
            }
#pragma unroll
            for (int mi = 0; mi < 4; mi++)
#pragma unroll
                for (int ni = 0; ni < 4; ni++) {
                    asm volatile(
                        "mma.sync.aligned.m16n8k8.row.col.f32.tf32.tf32.f32 "
                        "{%0,%1,%2,%3}, {%4,%5,%6,%7}, {%8,%9}, {%0,%1,%2,%3};\n"
                        : "+f"(c[mi][ni][0]), "+f"(c[mi][ni][1]),
                          "+f"(c[mi][ni][2]), "+f"(c[mi][ni][3])
                        : "r"(a[mi][0]), "r"(a[mi][1]), "r"(a[mi][2]), "r"(a[mi][3]),
                          "r"(b[ni][0]), "r"(b[ni][1]));
                }
        }
        __syncthreads();
    }

    // epilogue
    const int g = lane >> 2;
    const int l = lane & 3;
#pragma unroll
    for (int mi = 0; mi < 4; mi++) {
        int r0 = mBase + wm + mi * 16 + g;
        int r1 = r0 + 8;
#pragma unroll
        for (int ni = 0; ni < 4; ni++) {
            int col = nBase + wn + ni * 8 + 2 * l;
            if (r0 < M)
                *(float2*)&C[(size_t)r0 * N + col] = make_float2(c[mi][ni][0], c[mi][ni][1]);
            if (r1 < M)
                *(float2*)&C[(size_t)r1 * N + col] = make_float2(c[mi][ni][2], c[mi][ni][3]);
        }
    }
}

// ==================== attention logits per node ====================
__global__ void alpha_kernel(const float* __restrict__ h,
                             const float* __restrict__ a_s, const float* __restrict__ a_d,
                             float* __restrict__ as_out, float* __restrict__ ad_out,
                             int heads, int ch)
{
    int node = blockIdx.x;
    int w = threadIdx.x >> 5;
    int lane = threadIdx.x & 31;
    if (w >= heads) return;
    const float* hp = h + (size_t)node * heads * ch + w * ch;
    const float* asp = a_s + w * ch;
    const float* adp = a_d + w * ch;
    float ss = 0.f, sd = 0.f;
    for (int c = lane; c < ch; c += 32) {
        float v = hp[c];
        ss += v * asp[c];
        sd += v * adp[c];
    }
#pragma unroll
    for (int o = 16; o; o >>= 1) {
        ss += __shfl_xor_sync(0xffffffffu, ss, o);
        sd += __shfl_xor_sync(0xffffffffu, sd, o);
    }
    if (lane == 0) {
        as_out[node * heads + w] = ss;
        ad_out[node * heads + w] = sd;
    }
}

// ==================== CSR build ====================
__global__ void deg_kernel(const int* __restrict__ dst, int* __restrict__ deg, int E)
{
    int e = blockIdx.x * blockDim.x + threadIdx.x;
    if (e < E) atomicAdd(&deg[dst[e]], 1);
}

__global__ __launch_bounds__(1024) void scan_kernel(const int* __restrict__ deg,
                                                    int* __restrict__ rowstart, int n)
{
    __shared__ int warp_sums[32];
    __shared__ int s_carry;
    int t = threadIdx.x;
    int lane = t & 31, w = t >> 5;
    if (t == 0) s_carry = 0;
    __syncthreads();
    for (int base = 0; base < n; base += 1024) {
        int i = base + t;
        int x = (i < n) ? deg[i] : 0;
        int v = x;
#pragma unroll
        for (int o = 1; o < 32; o <<= 1) {
            int y = __shfl_up_sync(0xffffffffu, v, o);
            if (lane >= o) v += y;
        }
        if (lane == 31) warp_sums[w] = v;
        __syncthreads();
        if (w == 0) {
            int s = warp_sums[lane];
#pragma unroll
            for (int o = 1; o < 32; o <<= 1) {
                int y = __shfl_up_sync(0xffffffffu, s, o);
                if (lane >= o) s += y;
            }
            warp_sums[lane] = s;
        }
        __syncthreads();
        int prefix = s_carry + (w > 0 ? warp_sums[w - 1] : 0) + v - x; // exclusive
        if (i < n) rowstart[i] = prefix;
        __syncthreads();
        if (t == 0) s_carry += warp_sums[31];
        __syncthreads();
    }
    if (t == 0) rowstart[n] = s_carry;
}

__global__ void csr_scatter_kernel(const int* __restrict__ src, const int* __restrict__ dst,
                                   int* __restrict__ cursor, int* __restrict__ csr_src, int E)
{
    int e = blockIdx.x * blockDim.x + threadIdx.x;
    if (e >= E) return;
    int p = atomicAdd(&cursor[dst[e]], 1);
    csr_src[p] = src[e];
}

// ==================== fused softmax + aggregate + bias + ELU ====================
// One block (128 threads) per destination node.
template <int H>
__global__ __launch_bounds__(128) void gat_aggregate_kernel(
    const int* __restrict__ rowstart, const int* __restrict__ csr_src,
    const float* __restrict__ as_, const float* __restrict__ ad_,
    const float* __restrict__ hbuf, const float* __restrict__ bias,
    float* __restrict__ out, int do_elu)
{
    const int d = blockIdx.x;
    const int t = threadIdx.x;          // 0..127
    const int lane = t & 31, w = t >> 5;
    const int e0 = rowstart[d];
    const int deg = rowstart[d + 1] - e0;
    const int W = H * HID;

    __shared__ int   s_src[512];
    __shared__ float s_coef[H * 512];
    __shared__ float s_red[H * 4];

    float adv[H];
#pragma unroll
    for (int h = 0; h < H; h++) adv[h] = ad_[d * H + h];

    // pass 1: per-head max over incoming edges
    float mx[H];
#pragma unroll
    for (int h = 0; h < H; h++) mx[h] = -__int_as_float(0x7f800000);
    for (int j = t; j < deg; j += 128) {
        int s = csr_src[e0 + j];
#pragma unroll
        for (int h = 0; h < H; h++) {
            float v = as_[s * H + h] + adv[h];
            v = (v >= 0.f) ? v : NEG_SLOPE * v;
            mx[h] = fmaxf(mx[h], v);
        }
    }
#pragma unroll
    for (int h = 0; h < H; h++) {
#pragma unroll
        for (int o = 16; o; o >>= 1) mx[h] = fmaxf(mx[h], __shfl_xor_sync(0xffffffffu, mx[h], o));
        if (lane == 0) s_red[h * 4 + w] = mx[h];
    }
    __syncthreads();
#pragma unroll
    for (int h = 0; h < H; h++)
        mx[h] = fmaxf(fmaxf(s_red[h * 4 + 0], s_red[h * 4 + 1]),
                      fmaxf(s_red[h * 4 + 2], s_red[h * 4 + 3]));
    __syncthreads();

    // pass 2: per-head exp-sum
    float sm[H];
#pragma unroll
    for (int h = 0; h < H; h++) sm[h] = 0.f;
    for (int j = t; j < deg; j += 128) {
        int s = csr_src[e0 + j];
#pragma unroll
        for (int h = 0; h < H; h++) {
            float v = as_[s * H + h] + adv[h];
            v = (v >= 0.f) ? v : NEG_SLOPE * v;
            sm[h] += expf(v - mx[h]);
        }
    }
#pragma unroll
    for (int h = 0; h < H; h++) {
#pragma unroll
        for (int o = 16; o; o >>= 1) sm[h] += __shfl_xor_sync(0xffffffffu, sm[h], o);
        if (lane == 0) s_red[h * 4 + w] = sm[h];
    }
    __syncthreads();
    float inv[H];
#pragma unroll
    for (int h = 0; h < H; h++) {
        float s = s_red[h * 4 + 0] + s_red[h * 4 + 1] + s_red[h * 4 + 2] + s_red[h * 4 + 3];
        inv[h] = 1.f / (s + 1e-16f);
    }
    __syncthreads();

    // pass 3: windowed accumulate. Thread t owns H consecutive channels (one head).
    float acc[H];
#pragma unroll
    for (int h = 0; h < H; h++) acc[h] = 0.f;
    const int c0 = t * H;          // flat channel base (within one head since H|128 pattern)
    const int hd = c0 / HID;       // head of this thread's channels

    for (int w0 = 0; w0 < deg; w0 += 512) {
        int wn = min(512, deg - w0);
        for (int j = t; j < wn; j += 128) {
            int s = csr_src[e0 + w0 + j];
            s_src[j] = s;
#pragma unroll
            for (int h = 0; h < H; h++) {
                float v = as_[s * H + h] + adv[h];
                v = (v >= 0.f) ? v : NEG_SLOPE * v;
                s_coef[h * 512 + j] = expf(v - mx[h]) * inv[h];
            }
        }
        __syncthreads();
        for (int j = 0; j < wn; j++) {
            const float* hp = hbuf + (size_t)s_src[j] * W + c0;
            float cf = s_coef[hd * 512 + j];
            if (H == 4) {
                float4 v = *(const float4*)hp;
                acc[0] += v.x * cf; acc[1] += v.y * cf;
                acc[2] += v.z * cf; acc[3] += v.w * cf;
            } else {
                acc[0] += hp[0] * cf;
            }
        }
        __syncthreads();
    }

    // epilogue: bias + optional ELU, direct store
#pragma unroll
    for (int h = 0; h < H; h++) {
        float v = acc[h] + bias[c0 + h];
        if (do_elu) v = (v > 0.f) ? v : expm1f(v);
        out[(size_t)d * W + c0 + h] = v;
    }
}

// ==================== pooling ====================
__global__ void pool_sum_kernel(const float* __restrict__ node_emb, const int* __restrict__ batch,
                                float* __restrict__ pool, float* __restrict__ cnt, int n)
{
    int node = blockIdx.x;
    int t = threadIdx.x;
    int g = batch[node];
    atomicAdd(&pool[g * HID + t], node_emb[(size_t)node * HID + t]);
    if (t == 0) atomicAdd(&cnt[g], 1.0f);
}

__global__ void pool_div_kernel(const float* __restrict__ pool, const float* __restrict__ cnt,
                                float* __restrict__ out)
{
    int i = blockIdx.x * blockDim.x + threadIdx.x;
    if (i >= NGRAPH * HID) return;
    int g = i / HID;
    out[i] = pool[i] / fmaxf(cnt[g], 1.0f);
}

// ==================== host side ====================
static void run_gat_layer(const float* in, int fin,
                          const float* W, const float* a_s, const float* a_d, const float* bias,
                          int heads, float* out, int do_elu,
                          int n, const int* rowstart, const int* csr_src,
                          float* hbuf, float* asb, float* adb)
{
    const int width = heads * HID;

    dim3 ggrid(width / 128, (n + 127) / 128);
    tf32_gemm_kernel<<<ggrid, 256>>>(in, W, hbuf, n, fin, width);

    alpha_kernel<<<n, heads * 32>>>(hbuf, a_s, a_d, asb, adb, heads, HID);

    if (heads == 4)
        gat_aggregate_kernel<4><<<n, 128>>>(rowstart, csr_src, asb, adb, hbuf, bias, out, do_elu);
    else
        gat_aggregate_kernel<1><<<n, 128>>>(rowstart, csr_src, asb, adb, hbuf, bias, out, do_elu);
}

extern "C" void kernel_launch(void* const* d_in, const int* in_sizes, int n_in,
                              void* d_out, int out_size)
{
    const float* x     = (const float*)d_in[0];
    const int*   ei    = (const int*)d_in[1];
    const int*   batch = (const int*)d_in[2];
    const float* W1  = (const float*)d_in[3];
    const float* a1s = (const float*)d_in[4];
    const float* a1d = (const float*)d_in[5];
    const float* b1  = (const float*)d_in[6];
    const float* W2  = (const float*)d_in[7];
    const float* a2s = (const float*)d_in[8];
    const float* a2d = (const float*)d_in[9];
    const float* b2  = (const float*)d_in[10];
    const float* W3  = (const float*)d_in[11];
    const float* a3s = (const float*)d_in[12];
    const float* a3d = (const float*)d_in[13];
    const float* b3  = (const float*)d_in[14];

    const int n = in_sizes[0] / FIN;
    const int E = in_sizes[1] / 2;
    const int* src = ei;
    const int* dst = ei + E;

    float *hbuf, *actbuf, *asb, *adb, *poolb, *cntb;
    int *degb, *rowstartb, *cursorb, *csrsrcb;
    cudaGetSymbolAddress((void**)&hbuf,     g_h);
    cudaGetSymbolAddress((void**)&actbuf,   g_act);
    cudaGetSymbolAddress((void**)&asb,      g_as);
    cudaGetSymbolAddress((void**)&adb,      g_ad);
    cudaGetSymbolAddress((void**)&degb,     g_deg);
    cudaGetSymbolAddress((void**)&rowstartb,g_rowstart);
    cudaGetSymbolAddress((void**)&cursorb,  g_cursor);
    cudaGetSymbolAddress((void**)&csrsrcb,  g_csr_src);
    cudaGetSymbolAddress((void**)&poolb,    g_pool);
    cudaGetSymbolAddress((void**)&cntb,     g_cnt);

    float* node_emb  = (float*)d_out;
    float* graph_emb = (float*)d_out + (size_t)n * HID;

    // ---- CSR build (once, shared by all 3 layers) ----
    cudaMemsetAsync(degb, 0, (size_t)n * sizeof(int));
    deg_kernel<<<(E + 255) / 256, 256>>>(dst, degb, E);
    scan_kernel<<<1, 1024>>>(degb, rowstartb, n);
    cudaMemcpyAsync(cursorb, rowstartb, (size_t)n * sizeof(int), cudaMemcpyDeviceToDevice);
    csr_scatter_kernel<<<(E + 255) / 256, 256>>>(src, dst, cursorb, csrsrcb, E);

    // ---- layers ----
    run_gat_layer(x, FIN, W1, a1s, a1d, b1, HEADS, actbuf, 1,
                  n, rowstartb, csrsrcb, hbuf, asb, adb);
    run_gat_layer(actbuf, HEADS * HID, W2, a2s, a2d, b2, HEADS, actbuf, 1,
                  n, rowstartb, csrsrcb, hbuf, asb, adb);
    run_gat_layer(actbuf, HEADS * HID, W3, a3s, a3d, b3, 1, node_emb, 0,
                  n, rowstartb, csrsrcb, hbuf, asb, adb);

    // ---- global mean pool ----
    cudaMemsetAsync(poolb, 0, NGRAPH * HID * sizeof(float));
    cudaMemsetAsync(cntb, 0, NGRAPH * sizeof(float));
    pool_sum_kernel<<<n, HID>>>(node_emb, batch, poolb, cntb, n);
    pool_div_kernel<<<(NGRAPH * HID + 127) / 128, 128>>>(poolb, cntb, graph_emb);
}

// round 3
// speedup vs baseline: 5.1499x; 1.1931x over previous
#include <cuda_runtime.h>
#include <cuda_bf16.h>
#include <cstdint>
#include <cstddef>

#define NN 50000
#define EE 800000
#define FIN 256
#define HID 128
#define HEADS 4
#define NGRAPH 50
#define NEG_SLOPE 0.2f

// ---------------- scratch (device globals; no allocation allowed) -------------
__device__ float g_h[(size_t)NN * HEADS * HID];     // GEMM output per layer
__device__ float g_act[(size_t)NN * HEADS * HID];   // aggregated output / next input
__device__ float g_as[NN * HEADS];
__device__ float g_ad[NN * HEADS];
__device__ int   g_deg[NN];
__device__ int   g_rowstart[NN + 1];
__device__ int   g_cursor[NN];
__device__ int   g_csr_src[EE];
__device__ float g_coef[(size_t)EE * HEADS];        // normalized alpha, CSR order
__device__ float g_pool[NGRAPH * HID];
__device__ float g_cnt[NGRAPH];

// ==================== TF32 tensor-core GEMM + fused alpha epilogue ====================
// C[M,N] = A[M,K] @ B[K,N]. Each 128-col block tile covers exactly ONE head
// (N = H*128, nBase % 128 == 0), so per-row attention dots for that head are
// computed from the accumulator fragments and atomically accumulated.

__device__ __forceinline__ float to_tf32(float x) {
    float y;
    asm("cvt.rna.tf32.f32 %0, %1;" : "=f"(y) : "f"(x));
    return y;
}

__global__ __launch_bounds__(256) void tf32_gemm_alpha_kernel(
    const float* __restrict__ A, const float* __restrict__ B, float* __restrict__ C,
    int M, int K, int N,
    const float* __restrict__ a_src, const float* __restrict__ a_dst,  // [H][HID]
    float* __restrict__ as_out, float* __restrict__ ad_out, int H)
{
    __shared__ __align__(16) float As[128][36];
    __shared__ __align__(16) float Bs[32][136];

    const int tid  = threadIdx.x;
    const int lane = tid & 31;
    const int warp = tid >> 5;
    const int wm = (warp & 1) * 64;
    const int wn = (warp >> 1) * 32;

    const int mBase = blockIdx.y * 128;
    const int nBase = blockIdx.x * 128;

    float c[4][4][4];
#pragma unroll
    for (int mi = 0; mi < 4; mi++)
#pragma unroll
        for (int ni = 0; ni < 4; ni++)
#pragma unroll
            for (int q = 0; q < 4; q++) c[mi][ni][q] = 0.f;

    const int arow = tid >> 3;
    const int acol = (tid & 7) * 4;
    const int brow = tid >> 5;
    const int bcol = (tid & 31) * 4;

    for (int k0 = 0; k0 < K; k0 += 32) {
#pragma unroll
        for (int p = 0; p < 4; p++) {
            int r = arow + p * 32;
            int gr = mBase + r;
            float4 v = make_float4(0.f, 0.f, 0.f, 0.f);
            if (gr < M) v = *(const float4*)&A[(size_t)gr * K + k0 + acol];
            As[r][acol + 0] = to_tf32(v.x);
            As[r][acol + 1] = to_tf32(v.y);
            As[r][acol + 2] = to_tf32(v.z);
            As[r][acol + 3] = to_tf32(v.w);
        }
#pragma unroll
        for (int p = 0; p < 4; p++) {
            int r = brow + p * 8;
            float4 v = *(const float4*)&B[(size_t)(k0 + r) * N + nBase + bcol];
            Bs[r][bcol + 0] = to_tf32(v.x);
            Bs[r][bcol + 1] = to_tf32(v.y);
            Bs[r][bcol + 2] = to_tf32(v.z);
            Bs[r][bcol + 3] = to_tf32(v.w);
        }
        __syncthreads();

#pragma unroll
        for (int kk = 0; kk < 32; kk += 8) {
            uint32_t a[4][4], b[4][2];
            const int g = lane >> 2;
            const int l = lane & 3;
#pragma unroll
            for (int mi = 0; mi < 4; mi++) {
                int r = wm + mi * 16 + g;
                a[mi][0] = __float_as_uint(As[r][kk + l]);
                a[mi][1] = __float_as_uint(As[r + 8][kk + l]);
                a[mi][2] = __float_as_uint(As[r][kk + l + 4]);
                a[mi][3] = __float_as_uint(As[r + 8][kk + l + 4]);
            }
#pragma unroll
            for (int ni = 0; ni < 4; ni++) {
                int ncol = wn + ni * 8 + g;
                b[ni][0] = __float_as_uint(Bs[kk + l][ncol]);
                b[ni][1] = __float_as_uint(Bs[kk + l + 4][ncol]);
            }
#pragma unroll
            for (int mi = 0; mi < 4; mi++)
#pragma unroll
                for (int ni = 0; ni < 4; ni++) {
                    asm volatile(
                        "mma.sync.aligned.m16n8k8.row.col.f32.tf32.tf32.f32 "
                        "{%0,%1,%2,%3}, {%4,%5,%6,%7}, {%8,%9}, {%0,%1,%2,%3};\n"
                        : "+f"(c[mi][ni][0]), "+f"(c[mi][ni][1]),
                          "+f"(c[mi][ni][2]), "+f"(c[mi][ni][3])
                        : "r"(a[mi][0]), "r"(a[mi][1]), "r"(a[mi][2]), "r"(a[mi][3]),
                          "r"(b[ni][0]), "r"(b[ni][1]));
                }
        }
        __syncthreads();
    }

    const int g = lane >> 2;
    const int l = lane & 3;
    const int hh = nBase / HID;   // head owned by this block column

#pragma unroll
    for (int mi = 0; mi < 4; mi++) {
        int r0 = mBase + wm + mi * 16 + g;
        int r1 = r0 + 8;
        float ps0 = 0.f, pd0 = 0.f, ps1 = 0.f, pd1 = 0.f;
#pragma unroll
        for (int ni = 0; ni < 4; ni++) {
            int col = nBase + wn + ni * 8 + 2 * l;
            if (r0 < M)
                *(float2*)&C[(size_t)r0 * N + col] = make_float2(c[mi][ni][0], c[mi][ni][1]);
            if (r1 < M)
                *(float2*)&C[(size_t)r1 * N + col] = make_float2(c[mi][ni][2], c[mi][ni][3]);
            int cc = wn + ni * 8 + 2 * l;  // within-head channel
            float sa0 = a_src[hh * HID + cc],     sa1 = a_src[hh * HID + cc + 1];
            float da0 = a_dst[hh * HID + cc],     da1 = a_dst[hh * HID + cc + 1];
            ps0 += c[mi][ni][0] * sa0 + c[mi][ni][1] * sa1;
            pd0 += c[mi][ni][0] * da0 + c[mi][ni][1] * da1;
            ps1 += c[mi][ni][2] * sa0 + c[mi][ni][3] * sa1;
            pd1 += c[mi][ni][2] * da0 + c[mi][ni][3] * da1;
        }
        // reduce over the 4 lanes of this quad (same g, l=0..3)
#pragma unroll
        for (int o = 1; o <= 2; o <<= 1) {
            ps0 += __shfl_xor_sync(0xffffffffu, ps0, o);
            pd0 += __shfl_xor_sync(0xffffffffu, pd0, o);
            ps1 += __shfl_xor_sync(0xffffffffu, ps1, o);
            pd1 += __shfl_xor_sync(0xffffffffu, pd1, o);
        }
        if (l == 0) {
            if (r0 < M) {
                atomicAdd(&as_out[r0 * H + hh], ps0);
                atomicAdd(&ad_out[r0 * H + hh], pd0);
            }
            if (r1 < M) {
                atomicAdd(&as_out[r1 * H + hh], ps1);
                atomicAdd(&ad_out[r1 * H + hh], pd1);
            }
        }
    }
}

// ==================== CSR build ====================
__global__ void deg_kernel(const int* __restrict__ dst, int* __restrict__ deg, int E)
{
    int e = blockIdx.x * blockDim.x + threadIdx.x;
    if (e < E) atomicAdd(&deg[dst[e]], 1);
}

__global__ __launch_bounds__(1024) void scan_kernel(const int* __restrict__ deg,
                                                    int* __restrict__ rowstart, int n)
{
    __shared__ int warp_sums[32];
    __shared__ int s_carry;
    int t = threadIdx.x;
    int lane = t & 31, w = t >> 5;
    if (t == 0) s_carry = 0;
    __syncthreads();
    for (int base = 0; base < n; base += 1024) {
        int i = base + t;
        int x = (i < n) ? deg[i] : 0;
        int v = x;
#pragma unroll
        for (int o = 1; o < 32; o <<= 1) {
            int y = __shfl_up_sync(0xffffffffu, v, o);
            if (lane >= o) v += y;
        }
        if (lane == 31) warp_sums[w] = v;
        __syncthreads();
        if (w == 0) {
            int s = warp_sums[lane];
#pragma unroll
            for (int o = 1; o < 32; o <<= 1) {
                int y = __shfl_up_sync(0xffffffffu, s, o);
                if (lane >= o) s += y;
            }
            warp_sums[lane] = s;
        }
        __syncthreads();
        int prefix = s_carry + (w > 0 ? warp_sums[w - 1] : 0) + v - x;
        if (i < n) rowstart[i] = prefix;
        __syncthreads();
        if (t == 0) s_carry += warp_sums[31];
        __syncthreads();
    }
    if (t == 0) rowstart[n] = s_carry;
}

__global__ void csr_scatter_kernel(const int* __restrict__ src, const int* __restrict__ dst,
                                   int* __restrict__ cursor, int* __restrict__ csr_src, int E)
{
    int e = blockIdx.x * blockDim.x + threadIdx.x;
    if (e >= E) return;
    int p = atomicAdd(&cursor[dst[e]], 1);
    csr_src[p] = src[e];
}

// ==================== edge coefficient kernel (warp per node) ====================
// For each dst node: segment softmax of leaky_relu(as[src]+ad[dst]) over incoming
// edges; writes normalized alpha into coef[] in CSR order.
template <int H>
__global__ __launch_bounds__(128) void coef_kernel(
    const int* __restrict__ rowstart, const int* __restrict__ csr_src,
    const float* __restrict__ as_, const float* __restrict__ ad_,
    float* __restrict__ coef, int n)
{
    const int d = blockIdx.x * 4 + (threadIdx.x >> 5);
    const int lane = threadIdx.x & 31;
    if (d >= n) return;
    const int e0 = rowstart[d];
    const int deg = rowstart[d + 1] - e0;

    float adv[H];
#pragma unroll
    for (int h = 0; h < H; h++) adv[h] = ad_[d * H + h];

    float mx[H];
#pragma unroll
    for (int h = 0; h < H; h++) mx[h] = -__int_as_float(0x7f800000);
    for (int j = lane; j < deg; j += 32) {
        int s = __ldg(&csr_src[e0 + j]);
        if (H == 4) {
            float4 av = __ldg((const float4*)&as_[s * 4]);
            float v0 = av.x + adv[0]; v0 = (v0 >= 0.f) ? v0 : NEG_SLOPE * v0;
            float v1 = av.y + adv[1]; v1 = (v1 >= 0.f) ? v1 : NEG_SLOPE * v1;
            float v2 = av.z + adv[2]; v2 = (v2 >= 0.f) ? v2 : NEG_SLOPE * v2;
            float v3 = av.w + adv[3]; v3 = (v3 >= 0.f) ? v3 : NEG_SLOPE * v3;
            mx[0] = fmaxf(mx[0], v0); mx[1] = fmaxf(mx[1], v1);
            mx[2] = fmaxf(mx[2], v2); mx[3] = fmaxf(mx[3], v3);
        } else {
            float v = __ldg(&as_[s]) + adv[0];
            v = (v >= 0.f) ? v : NEG_SLOPE * v;
            mx[0] = fmaxf(mx[0], v);
        }
    }
#pragma unroll
    for (int h = 0; h < H; h++)
#pragma unroll
        for (int o = 16; o; o >>= 1)
            mx[h] = fmaxf(mx[h], __shfl_xor_sync(0xffffffffu, mx[h], o));

    float sm[H];
#pragma unroll
    for (int h = 0; h < H; h++) sm[h] = 0.f;
    for (int j = lane; j < deg; j += 32) {
        int s = __ldg(&csr_src[e0 + j]);
        if (H == 4) {
            float4 av = __ldg((const float4*)&as_[s * 4]);
            float v0 = av.x + adv[0]; v0 = (v0 >= 0.f) ? v0 : NEG_SLOPE * v0;
            float v1 = av.y + adv[1]; v1 = (v1 >= 0.f) ? v1 : NEG_SLOPE * v1;
            float v2 = av.z + adv[2]; v2 = (v2 >= 0.f) ? v2 : NEG_SLOPE * v2;
            float v3 = av.w + adv[3]; v3 = (v3 >= 0.f) ? v3 : NEG_SLOPE * v3;
            sm[0] += expf(v0 - mx[0]); sm[1] += expf(v1 - mx[1]);
            sm[2] += expf(v2 - mx[2]); sm[3] += expf(v3 - mx[3]);
        } else {
            float v = __ldg(&as_[s]) + adv[0];
            v = (v >= 0.f) ? v : NEG_SLOPE * v;
            sm[0] += expf(v - mx[0]);
        }
    }
#pragma unroll
    for (int h = 0; h < H; h++)
#pragma unroll
        for (int o = 16; o; o >>= 1)
            sm[h] += __shfl_xor_sync(0xffffffffu, sm[h], o);

    float inv[H];
#pragma unroll
    for (int h = 0; h < H; h++) inv[h] = 1.f / (sm[h] + 1e-16f);

    for (int j = lane; j < deg; j += 32) {
        int s = __ldg(&csr_src[e0 + j]);
        if (H == 4) {
            float4 av = __ldg((const float4*)&as_[s * 4]);
            float v0 = av.x + adv[0]; v0 = (v0 >= 0.f) ? v0 : NEG_SLOPE * v0;
            float v1 = av.y + adv[1]; v1 = (v1 >= 0.f) ? v1 : NEG_SLOPE * v1;
            float v2 = av.z + adv[2]; v2 = (v2 >= 0.f) ? v2 : NEG_SLOPE * v2;
            float v3 = av.w + adv[3]; v3 = (v3 >= 0.f) ? v3 : NEG_SLOPE * v3;
            float4 cf;
            cf.x = expf(v0 - mx[0]) * inv[0];
            cf.y = expf(v1 - mx[1]) * inv[1];
            cf.z = expf(v2 - mx[2]) * inv[2];
            cf.w = expf(v3 - mx[3]) * inv[3];
            *(float4*)&coef[(size_t)(e0 + j) * 4] = cf;
        } else {
            float v = __ldg(&as_[s]) + adv[0];
            v = (v >= 0.f) ? v : NEG_SLOPE * v;
            coef[e0 + j] = expf(v - mx[0]) * inv[0];
        }
    }
}

// ==================== SpMM aggregate + bias + ELU (block per node) ====================
template <int H>
__global__ __launch_bounds__(128) void spmm_kernel(
    const int* __restrict__ rowstart, const int* __restrict__ csr_src,
    const float* __restrict__ coef, const float* __restrict__ hbuf,
    const float* __restrict__ bias, float* __restrict__ out, int do_elu)
{
    const int d = blockIdx.x;
    const int t = threadIdx.x;
    const int e0 = rowstart[d];
    const int deg = rowstart[d + 1] - e0;
    const int W = H * HID;
    const int c0 = t * H;               // this thread's channel base
    const int hd = (H == 4) ? (t >> 5) : 0;   // head of those channels

    float acc0 = 0.f, acc1 = 0.f, acc2 = 0.f, acc3 = 0.f;

#pragma unroll 4
    for (int j = 0; j < deg; j++) {
        int s = __ldg(&csr_src[e0 + j]);                          // broadcast
        float cf = __ldg(&coef[(size_t)(e0 + j) * H + hd]);       // broadcast/warp
        const float* hp = hbuf + (size_t)s * W + c0;
        if (H == 4) {
            float4 v = __ldg((const float4*)hp);
            acc0 += v.x * cf; acc1 += v.y * cf;
            acc2 += v.z * cf; acc3 += v.w * cf;
        } else {
            acc0 += __ldg(hp) * cf;
        }
    }

    if (H == 4) {
        float4 b = *(const float4*)&bias[c0];
        float v0 = acc0 + b.x, v1 = acc1 + b.y, v2 = acc2 + b.z, v3 = acc3 + b.w;
        if (do_elu) {
            v0 = (v0 > 0.f) ? v0 : expm1f(v0);
            v1 = (v1 > 0.f) ? v1 : expm1f(v1);
            v2 = (v2 > 0.f) ? v2 : expm1f(v2);
            v3 = (v3 > 0.f) ? v3 : expm1f(v3);
        }
        *(float4*)&out[(size_t)d * W + c0] = make_float4(v0, v1, v2, v3);
    } else {
        float v = acc0 + bias[c0];
        if (do_elu) v = (v > 0.f) ? v : expm1f(v);
        out[(size_t)d * W + c0] = v;
    }
}

// ==================== pooling ====================
__global__ void pool_sum_kernel(const float* __restrict__ node_emb, const int* __restrict__ batch,
                                float* __restrict__ pool, float* __restrict__ cnt, int n)
{
    int node = blockIdx.x;
    int t = threadIdx.x;
    int g = batch[node];
    atomicAdd(&pool[g * HID + t], node_emb[(size_t)node * HID + t]);
    if (t == 0) atomicAdd(&cnt[g], 1.0f);
}

__global__ void pool_div_kernel(const float* __restrict__ pool, const float* __restrict__ cnt,
                                float* __restrict__ out)
{
    int i = blockIdx.x * blockDim.x + threadIdx.x;
    if (i >= NGRAPH * HID) return;
    int g = i / HID;
    out[i] = pool[i] / fmaxf(cnt[g], 1.0f);
}

// ==================== host side ====================
static void run_gat_layer(const float* in, int fin,
                          const float* W, const float* a_s, const float* a_d, const float* bias,
                          int heads, float* out, int do_elu,
                          int n, const int* rowstart, const int* csr_src,
                          float* hbuf, float* asb, float* adb, float* coefb)
{
    const int width = heads * HID;

    cudaMemsetAsync(asb, 0, (size_t)n * heads * sizeof(float));
    cudaMemsetAsync(adb, 0, (size_t)n * heads * sizeof(float));

    dim3 ggrid(width / 128, (n + 127) / 128);
    tf32_gemm_alpha_kernel<<<ggrid, 256>>>(in, W, hbuf, n, fin, width,
                                           a_s, a_d, asb, adb, heads);

    int cgrid = (n + 3) / 4;
    if (heads == 4) {
        coef_kernel<4><<<cgrid, 128>>>(rowstart, csr_src, asb, adb, coefb, n);
        spmm_kernel<4><<<n, 128>>>(rowstart, csr_src, coefb, hbuf, bias, out, do_elu);
    } else {
        coef_kernel<1><<<cgrid, 128>>>(rowstart, csr_src, asb, adb, coefb, n);
        spmm_kernel<1><<<n, 128>>>(rowstart, csr_src, coefb, hbuf, bias, out, do_elu);
    }
}

extern "C" void kernel_launch(void* const* d_in, const int* in_sizes, int n_in,
                              void* d_out, int out_size)
{
    const float* x     = (const float*)d_in[0];
    const int*   ei    = (const int*)d_in[1];
    const int*   batch = (const int*)d_in[2];
    const float* W1  = (const float*)d_in[3];
    const float* a1s = (const float*)d_in[4];
    const float* a1d = (const float*)d_in[5];
    const float* b1  = (const float*)d_in[6];
    const float* W2  = (const float*)d_in[7];
    const float* a2s = (const float*)d_in[8];
    const float* a2d = (const float*)d_in[9];
    const float* b2  = (const float*)d_in[10];
    const float* W3  = (const float*)d_in[11];
    const float* a3s = (const float*)d_in[12];
    const float* a3d = (const float*)d_in[13];
    const float* b3  = (const float*)d_in[14];

    const int n = in_sizes[0] / FIN;
    const int E = in_sizes[1] / 2;
    const int* src = ei;
    const int* dst = ei + E;

    float *hbuf, *actbuf, *asb, *adb, *coefb, *poolb, *cntb;
    int *degb, *rowstartb, *cursorb, *csrsrcb;
    cudaGetSymbolAddress((void**)&hbuf,      g_h);
    cudaGetSymbolAddress((void**)&actbuf,    g_act);
    cudaGetSymbolAddress((void**)&asb,       g_as);
    cudaGetSymbolAddress((void**)&adb,       g_ad);
    cudaGetSymbolAddress((void**)&degb,      g_deg);
    cudaGetSymbolAddress((void**)&rowstartb, g_rowstart);
    cudaGetSymbolAddress((void**)&cursorb,   g_cursor);
    cudaGetSymbolAddress((void**)&csrsrcb,   g_csr_src);
    cudaGetSymbolAddress((void**)&coefb,     g_coef);
    cudaGetSymbolAddress((void**)&poolb,     g_pool);
    cudaGetSymbolAddress((void**)&cntb,      g_cnt);

    float* node_emb  = (float*)d_out;
    float* graph_emb = (float*)d_out + (size_t)n * HID;

    // ---- CSR build (once, shared by all 3 layers) ----
    cudaMemsetAsync(degb, 0, (size_t)n * sizeof(int));
    deg_kernel<<<(E + 255) / 256, 256>>>(dst, degb, E);
    scan_kernel<<<1, 1024>>>(degb, rowstartb, n);
    cudaMemcpyAsync(cursorb, rowstartb, (size_t)n * sizeof(int), cudaMemcpyDeviceToDevice);
    csr_scatter_kernel<<<(E + 255) / 256, 256>>>(src, dst, cursorb, csrsrcb, E);

    // ---- layers ----
    run_gat_layer(x, FIN, W1, a1s, a1d, b1, HEADS, actbuf, 1,
                  n, rowstartb, csrsrcb, hbuf, asb, adb, coefb);
    run_gat_layer(actbuf, HEADS * HID, W2, a2s, a2d, b2, HEADS, actbuf, 1,
                  n, rowstartb, csrsrcb, hbuf, asb, adb, coefb);
    run_gat_layer(actbuf, HEADS * HID, W3, a3s, a3d, b3, 1, node_emb, 0,
                  n, rowstartb, csrsrcb, hbuf, asb, adb, coefb);

    // ---- global mean pool ----
    cudaMemsetAsync(poolb, 0, NGRAPH * HID * sizeof(float));
    cudaMemsetAsync(cntb, 0, NGRAPH * sizeof(float));
    pool_sum_kernel<<<n, HID>>>(node_emb, batch, poolb, cntb, n);
    pool_div_kernel<<<(NGRAPH * HID + 127) / 128, 128>>>(poolb, cntb, graph_emb);
}